// round 1
// baseline (speedup 1.0000x reference)
#include <cuda_runtime.h>

#define S_LEN 512
#define HORIZ 64
#define T_LEN 576   // S_LEN + HORIZ
#define HID   32
#define FEAT  4

// Scratch for deferred attention: h[t] for t = 0..510
__device__ float gH[S_LEN * HID];

__device__ __forceinline__ float sigmoid_f(float x) {
    return 1.0f / (1.0f + __expf(-x));
}
__device__ __forceinline__ float tanh_f(float x) {
    // tanh(x) = 2*sigmoid(2x) - 1 ; correct limits at +-inf
    return 2.0f / (1.0f + __expf(-2.0f * x)) - 1.0f;
}

__device__ __forceinline__ float warp_sum(float v) {
#pragma unroll
    for (int d = 16; d; d >>= 1) v += __shfl_xor_sync(0xffffffffu, v, d);
    return v;
}

// Collapsed attention + output head for one step, one warp, lane = hidden unit.
// out[i] = tanh(C*h[i] + D + exclpref(r)/(exclpref(av)+1e-9) + b_out)
// mu = <out,Wmu>+bmu ; sigma = softplus(<out,Wsig>+bsig)+1e-6 ; sample = mu+sigma*eps
__device__ __forceinline__ void attn_step(
    float h, int lane,
    float A, float B, float C, float D, float C2, float D2,
    float bo, float wmu, float bm, float wsig, float bs,
    float epsv, float* mu_o, float* sig_o, float* samp_o)
{
    float av = __expf(fmaf(A, h, B));
    float rv = av * fmaf(C2, h, D2);
    float pa = av, pr = rv;
#pragma unroll
    for (int d = 1; d < 32; d <<= 1) {
        float ta = __shfl_up_sync(0xffffffffu, pa, d);
        float tr = __shfl_up_sync(0xffffffffu, pr, d);
        if (lane >= d) { pa += ta; pr += tr; }
    }
    float exa = pa - av;          // exclusive prefix of av
    float exr = pr - rv;          // exclusive prefix of r
    float o = tanh_f(fmaf(C, h, D) + __fdividef(exr, exa + 1e-9f) + bo);
    float pm = o * wmu, ps = o * wsig;
#pragma unroll
    for (int d = 16; d; d >>= 1) {
        pm += __shfl_xor_sync(0xffffffffu, pm, d);
        ps += __shfl_xor_sync(0xffffffffu, ps, d);
    }
    float mu  = pm + bm;
    float sig = log1pf(__expf(ps + bs)) + 1e-6f;
    *mu_o = mu;
    *sig_o = sig;
    *samp_o = fmaf(sig, epsv, mu);
}

// ---------------------------------------------------------------------------
// Kernel 1: single warp, full sequential scan.
//   t = 0..510   : LSTM only (yin = y[t]); store h to gH (attention deferred)
//   t = 511..575 : LSTM + inline attention (sample feedback is live)
// ---------------------------------------------------------------------------
extern "C" __global__ void __launch_bounds__(32, 1) deepar_seq(
    const float* __restrict__ X,    const float* __restrict__ y,
    const float* __restrict__ Xf,   const float* __restrict__ eps,
    const float* __restrict__ W_ye, const float* __restrict__ b_ye,
    const float* __restrict__ W_ih, const float* __restrict__ W_hh,
    const float* __restrict__ b_ih, const float* __restrict__ b_hh,
    const float* __restrict__ W_ef, const float* __restrict__ b_ef,
    const float* __restrict__ W_av, const float* __restrict__ b_av,
    const float* __restrict__ W_out,const float* __restrict__ b_out,
    const float* __restrict__ W_mu, const float* __restrict__ b_mu,
    const float* __restrict__ W_sig,const float* __restrict__ b_sig,
    float* __restrict__ out)
{
    __shared__ float sx[T_LEN * FEAT];
    __shared__ float sy[S_LEN];
    __shared__ float se[T_LEN];
    __shared__ float sh[HID];

    const int j = threadIdx.x;   // lane = hidden unit

    // ---- preload small inputs to shared ----
    for (int i = j; i < S_LEN * FEAT; i += 32) sx[i] = X[i];
    for (int i = j; i < HORIZ * FEAT; i += 32) sx[S_LEN * FEAT + i] = Xf[i];
    for (int i = j; i < S_LEN; i += 32) sy[i] = y[i];
    for (int i = j; i < T_LEN; i += 32) se[i] = eps[i];

    // ---- per-lane gate weights in registers ----
    // gate order (torch): i=rows 0..31, f=32..63, g=64..95, o=96..127
    float wh[4][32];    // W_hh rows for this lane's 4 gates
    float wx[4][4];     // W_ih[:, 0:4] (x features)
    float ug[4];        // W_ih[:, 4:36] @ W_ye  (yin coefficient)
    float bg[4];        // b_ih + b_hh + W_ih[:, 4:36] @ b_ye
#pragma unroll
    for (int g = 0; g < 4; g++) {
        int row = g * 32 + j;
#pragma unroll
        for (int k = 0; k < 32; k++) wh[g][k] = W_hh[row * 32 + k];
#pragma unroll
        for (int k = 0; k < 4; k++)  wx[g][k] = W_ih[row * 36 + k];
        float u = 0.f, b = b_ih[row] + b_hh[row];
#pragma unroll
        for (int k = 0; k < 32; k++) {
            float w = W_ih[row * 36 + 4 + k];
            u = fmaf(w, W_ye[k], u);
            b = fmaf(w, b_ye[k], b);
        }
        ug[g] = u; bg[g] = b;
    }

    // ---- collapsed attention scalars ----
    float wef = W_ef[j], bef = b_ef[j], wav = W_av[j];
    float wo1 = W_out[j], wo2 = W_out[32 + j];
    float A  = warp_sum(wef * wav);
    float B  = warp_sum(bef * wav) + b_av[0];
    float C  = warp_sum(wef * wo1);
    float D  = warp_sum(bef * wo1);
    float C2 = warp_sum(wef * wo2);
    float D2 = warp_sum(bef * wo2);
    float bo = b_out[0], bm = b_mu[0], bs = b_sig[0];
    float wmu = W_mu[j], wsig = W_sig[j];

    float h = 0.f, c = 0.f, sample = 0.f;
    sh[j] = 0.f;
    __syncwarp();

    for (int t = 0; t < T_LEN; t++) {
        float yin = (t < S_LEN) ? sy[t] : sample;
        float x0 = sx[t * 4 + 0], x1 = sx[t * 4 + 1];
        float x2 = sx[t * 4 + 2], x3 = sx[t * 4 + 3];

        float a0 = fmaf(ug[0], yin, bg[0]);
        float a1 = fmaf(ug[1], yin, bg[1]);
        float a2 = fmaf(ug[2], yin, bg[2]);
        float a3 = fmaf(ug[3], yin, bg[3]);
        a0 = fmaf(wx[0][0], x0, a0); a0 = fmaf(wx[0][1], x1, a0);
        a0 = fmaf(wx[0][2], x2, a0); a0 = fmaf(wx[0][3], x3, a0);
        a1 = fmaf(wx[1][0], x0, a1); a1 = fmaf(wx[1][1], x1, a1);
        a1 = fmaf(wx[1][2], x2, a1); a1 = fmaf(wx[1][3], x3, a1);
        a2 = fmaf(wx[2][0], x0, a2); a2 = fmaf(wx[2][1], x1, a2);
        a2 = fmaf(wx[2][2], x2, a2); a2 = fmaf(wx[2][3], x3, a2);
        a3 = fmaf(wx[3][0], x0, a3); a3 = fmaf(wx[3][1], x1, a3);
        a3 = fmaf(wx[3][2], x2, a3); a3 = fmaf(wx[3][3], x3, a3);

        // h broadcast from shared as float4, kept in registers
        float hr[32];
        {
            const float4* sh4 = (const float4*)sh;
#pragma unroll
            for (int q = 0; q < 8; q++) {
                float4 v = sh4[q];
                hr[4 * q + 0] = v.x; hr[4 * q + 1] = v.y;
                hr[4 * q + 2] = v.z; hr[4 * q + 3] = v.w;
            }
        }
#pragma unroll
        for (int k = 0; k < 32; k++) {
            float hk = hr[k];
            a0 = fmaf(wh[0][k], hk, a0);
            a1 = fmaf(wh[1][k], hk, a1);
            a2 = fmaf(wh[2][k], hk, a2);
            a3 = fmaf(wh[3][k], hk, a3);
        }

        float gi = sigmoid_f(a0);
        float gf = sigmoid_f(a1);
        float gg = tanh_f(a2);
        float go = sigmoid_f(a3);
        c = fmaf(gf, c, gi * gg);
        h = go * tanh_f(c);

        __syncwarp();            // all lanes done reading old sh
        sh[j] = h;
        __syncwarp();            // new h visible to all lanes next iter

        if (t < S_LEN - 1) {
            gH[t * 32 + j] = h;  // attention deferred to parallel kernel
        } else {
            float mu, sig;
            attn_step(h, j, A, B, C, D, C2, D2, bo, wmu, bm, wsig, bs,
                      se[t], &mu, &sig, &sample);
            if (j == 0) {
                out[HORIZ + t]        = mu;     // mu block
                out[HORIZ + T_LEN + t] = sig;   // sigma block
                if (t < S_LEN - 1 + HORIZ)      // t in [511, 574]
                    out[t - (S_LEN - 1)] = sample;  // ypred block
            }
        }
    }
}

// ---------------------------------------------------------------------------
// Kernel 2: deferred attention for t = 0..510, one warp per t (all parallel).
// ---------------------------------------------------------------------------
extern "C" __global__ void deepar_att(
    const float* __restrict__ W_ef, const float* __restrict__ b_ef,
    const float* __restrict__ W_av, const float* __restrict__ b_av,
    const float* __restrict__ W_out,const float* __restrict__ b_out,
    const float* __restrict__ W_mu, const float* __restrict__ b_mu,
    const float* __restrict__ W_sig,const float* __restrict__ b_sig,
    float* __restrict__ out)
{
    const int warp = (blockIdx.x * blockDim.x + threadIdx.x) >> 5;
    const int lane = threadIdx.x & 31;
    if (warp >= S_LEN - 1) return;

    float wef = W_ef[lane], bef = b_ef[lane], wav = W_av[lane];
    float wo1 = W_out[lane], wo2 = W_out[32 + lane];
    float A  = warp_sum(wef * wav);
    float B  = warp_sum(bef * wav) + b_av[0];
    float C  = warp_sum(wef * wo1);
    float D  = warp_sum(bef * wo1);
    float C2 = warp_sum(wef * wo2);
    float D2 = warp_sum(bef * wo2);

    float h = gH[warp * 32 + lane];
    float mu, sig, samp;
    attn_step(h, lane, A, B, C, D, C2, D2, b_out[0],
              W_mu[lane], b_mu[0], W_sig[lane], b_sig[0],
              0.f, &mu, &sig, &samp);
    if (lane == 0) {
        out[HORIZ + warp]         = mu;
        out[HORIZ + T_LEN + warp] = sig;
    }
}

extern "C" void kernel_launch(void* const* d_in, const int* in_sizes, int n_in,
                              void* d_out, int out_size)
{
    const float* X     = (const float*)d_in[0];
    const float* y     = (const float*)d_in[1];
    const float* Xf    = (const float*)d_in[2];
    const float* eps   = (const float*)d_in[3];
    const float* W_ye  = (const float*)d_in[4];
    const float* b_ye  = (const float*)d_in[5];
    const float* W_ih  = (const float*)d_in[6];
    const float* W_hh  = (const float*)d_in[7];
    const float* b_ih  = (const float*)d_in[8];
    const float* b_hh  = (const float*)d_in[9];
    const float* W_ef  = (const float*)d_in[10];
    const float* b_ef  = (const float*)d_in[11];
    const float* W_av  = (const float*)d_in[12];
    const float* b_av  = (const float*)d_in[13];
    const float* W_out = (const float*)d_in[14];
    const float* b_out = (const float*)d_in[15];
    const float* W_mu  = (const float*)d_in[16];
    const float* b_mu  = (const float*)d_in[17];
    const float* W_sig = (const float*)d_in[18];
    const float* b_sig = (const float*)d_in[19];
    float* out = (float*)d_out;

    deepar_seq<<<1, 32>>>(X, y, Xf, eps, W_ye, b_ye, W_ih, W_hh, b_ih, b_hh,
                          W_ef, b_ef, W_av, b_av, W_out, b_out,
                          W_mu, b_mu, W_sig, b_sig, out);
    // 511 warps needed; 64 blocks x 256 threads = 512 warps
    deepar_att<<<64, 256>>>(W_ef, b_ef, W_av, b_av, W_out, b_out,
                            W_mu, b_mu, W_sig, b_sig, out);
}

// round 2
// speedup vs baseline: 2.3338x; 2.3338x over previous
#include <cuda_runtime.h>
#include <cstdint>

#define S_LEN 512
#define HORIZ 64
#define T_LEN 576   // S_LEN + HORIZ
#define HID   32
#define FEAT  4

// Scratch for deferred attention: h[t] for t = 0..510
__device__ float gH[S_LEN * HID];

// ---------------- packed f32x2 helpers ----------------
#define MUL2(d, a, b) \
    asm("mul.rn.f32x2 %0, %1, %2;" : "=l"(d) : "l"(a), "l"(b))
#define FMA2(d, a, b, c) \
    asm("fma.rn.f32x2 %0, %1, %2, %3;" : "=l"(d) : "l"(a), "l"(b), "l"(c))
#define ADD2(d, a, b) \
    asm("add.rn.f32x2 %0, %1, %2;" : "=l"(d) : "l"(a), "l"(b))
#define PACK2(d, lo, hi) \
    asm("mov.b64 %0, {%1, %2};" : "=l"(d) : "f"(lo), "f"(hi))
#define UNPACK2(lo, hi, v) \
    asm("mov.b64 {%0, %1}, %2;" : "=f"(lo), "=f"(hi) : "l"(v))

__device__ __forceinline__ float tanh_fast(float x) {
    float r; asm("tanh.approx.f32 %0, %1;" : "=f"(r) : "f"(x)); return r;
}
__device__ __forceinline__ float tanh_acc(float x) {
    // accurate-ish tanh for output head
    return 2.0f / (1.0f + __expf(-2.0f * x)) - 1.0f;
}

__device__ __forceinline__ float warp_sum(float v) {
#pragma unroll
    for (int d = 16; d; d >>= 1) v += __shfl_xor_sync(0xffffffffu, v, d);
    return v;
}

// Collapsed attention + output head, one warp, lane = hidden unit.
__device__ __forceinline__ void attn_step(
    float h, int lane,
    float A, float B, float C, float D, float C2, float D2,
    float bo, float wmu, float bm, float wsig, float bs,
    float epsv, float* mu_o, float* sig_o, float* samp_o)
{
    float av = __expf(fmaf(A, h, B));
    float rv = av * fmaf(C2, h, D2);
    float pa = av, pr = rv;
#pragma unroll
    for (int d = 1; d < 32; d <<= 1) {
        float ta = __shfl_up_sync(0xffffffffu, pa, d);
        float tr = __shfl_up_sync(0xffffffffu, pr, d);
        if (lane >= d) { pa += ta; pr += tr; }
    }
    float exa = pa - av;          // exclusive prefix of av
    float exr = pr - rv;          // exclusive prefix of r
    float o = tanh_acc(fmaf(C, h, D) + __fdividef(exr, exa + 1e-9f) + bo);
    float pm = o * wmu, ps = o * wsig;
#pragma unroll
    for (int d = 16; d; d >>= 1) {
        pm += __shfl_xor_sync(0xffffffffu, pm, d);
        ps += __shfl_xor_sync(0xffffffffu, ps, d);
    }
    float mu  = pm + bm;
    float sig = log1pf(__expf(ps + bs)) + 1e-6f;
    *mu_o = mu;
    *sig_o = sig;
    *samp_o = fmaf(sig, epsv, mu);
}

// ---------------------------------------------------------------------------
// Kernel 1: 4 warps. Warp g owns gate g (i,f,g,o); thread (g,j) owns gate row
// g*32+j. Cell state c_j is replicated deterministically in all 4 warps.
//   t = 0..510   : LSTM only; h stored to gH (attention deferred)
//   t = 511..575 : LSTM + inline attention (redundant per-warp, shuffle-based)
// ---------------------------------------------------------------------------
extern "C" __global__ void __launch_bounds__(128, 1) deepar_seq(
    const float* __restrict__ X,    const float* __restrict__ y,
    const float* __restrict__ Xf,   const float* __restrict__ eps,
    const float* __restrict__ W_ye, const float* __restrict__ b_ye,
    const float* __restrict__ W_ih, const float* __restrict__ W_hh,
    const float* __restrict__ b_ih, const float* __restrict__ b_hh,
    const float* __restrict__ W_ef, const float* __restrict__ b_ef,
    const float* __restrict__ W_av, const float* __restrict__ b_av,
    const float* __restrict__ W_out,const float* __restrict__ b_out,
    const float* __restrict__ W_mu, const float* __restrict__ b_mu,
    const float* __restrict__ W_sig,const float* __restrict__ b_sig,
    float* __restrict__ out)
{
    __shared__ __align__(16) float sx[T_LEN * FEAT];
    __shared__ float sy[S_LEN];
    __shared__ float se[T_LEN];
    __shared__ __align__(8) float sh[HID];
    __shared__ float sAct[128];

    const int tid = threadIdx.x;
    const int g = tid >> 5;      // gate / warp id
    const int j = tid & 31;      // hidden unit / lane

    // ---- preload small inputs to shared ----
    for (int i = tid; i < S_LEN * FEAT; i += 128) sx[i] = X[i];
    for (int i = tid; i < HORIZ * FEAT; i += 128) sx[S_LEN * FEAT + i] = Xf[i];
    for (int i = tid; i < S_LEN; i += 128) sy[i] = y[i];
    for (int i = tid; i < T_LEN; i += 128) se[i] = eps[i];

    // ---- per-thread gate-row weights (packed f32x2 along k) ----
    const int row = g * 32 + j;   // torch gate order: i,f,g,o
    uint64_t wh2[16];
    {
        const float2* wr = (const float2*)(W_hh + row * 32);
#pragma unroll
        for (int k = 0; k < 16; k++) {
            float2 v = wr[k];
            PACK2(wh2[k], v.x, v.y);
        }
    }
    float wx0 = W_ih[row * 36 + 0], wx1 = W_ih[row * 36 + 1];
    float wx2 = W_ih[row * 36 + 2], wx3 = W_ih[row * 36 + 3];
    float ug = 0.f, bg = b_ih[row] + b_hh[row];
#pragma unroll
    for (int k = 0; k < 32; k++) {
        float w = W_ih[row * 36 + 4 + k];
        ug = fmaf(w, W_ye[k], ug);
        bg = fmaf(w, b_ye[k], bg);
    }
    // activation affine: gate g==2 -> tanh(x); else sigmoid(x)=0.5*tanh(0.5x)+0.5
    const float act_s = (g == 2) ? 1.0f : 0.5f;
    const float act_b = (g == 2) ? 0.0f : 0.5f;

    // ---- collapsed attention scalars (identical in every warp) ----
    float wef = W_ef[j], bef = b_ef[j], wav = W_av[j];
    float wo1 = W_out[j], wo2 = W_out[32 + j];
    float A  = warp_sum(wef * wav);
    float B  = warp_sum(bef * wav) + b_av[0];
    float C  = warp_sum(wef * wo1);
    float D  = warp_sum(bef * wo1);
    float C2 = warp_sum(wef * wo2);
    float D2 = warp_sum(bef * wo2);
    float bo = b_out[0], bm = b_mu[0], bs = b_sig[0];
    float wmu = W_mu[j], wsig = W_sig[j];

    uint32_t sh_addr;
    asm("{ .reg .u64 t0; cvta.to.shared.u64 t0, %1; cvt.u32.u64 %0, t0; }"
        : "=r"(sh_addr) : "l"(sh));

    float c = 0.f, sample = 0.f;
    if (tid < 32) sh[tid] = 0.f;
    __syncthreads();

    for (int t = 0; t < T_LEN; t++) {
        float yin = (t < S_LEN) ? sy[t] : sample;
        float4 xv = ((const float4*)sx)[t];

        // input part of preactivation (overlaps the shared h loads)
        float base = fmaf(ug, yin, bg);
        base = fmaf(wx0, xv.x, base);
        base = fmaf(wx1, xv.y, base);
        base = fmaf(wx2, xv.z, base);
        base = fmaf(wx3, xv.w, base);

        // h pairs from shared
        uint64_t hp[16];
#pragma unroll
        for (int k = 0; k < 16; k++)
            asm volatile("ld.shared.b64 %0, [%1];"
                         : "=l"(hp[k]) : "r"(sh_addr + 8u * k));

        // packed dot product: 4 chains of depth 4
        uint64_t acc0, acc1, acc2, acc3;
        MUL2(acc0, wh2[0], hp[0]);
        MUL2(acc1, wh2[1], hp[1]);
        MUL2(acc2, wh2[2], hp[2]);
        MUL2(acc3, wh2[3], hp[3]);
#pragma unroll
        for (int s = 1; s < 4; s++) {
            FMA2(acc0, wh2[s * 4 + 0], hp[s * 4 + 0], acc0);
            FMA2(acc1, wh2[s * 4 + 1], hp[s * 4 + 1], acc1);
            FMA2(acc2, wh2[s * 4 + 2], hp[s * 4 + 2], acc2);
            FMA2(acc3, wh2[s * 4 + 3], hp[s * 4 + 3], acc3);
        }
        ADD2(acc0, acc0, acc1);
        ADD2(acc2, acc2, acc3);
        ADD2(acc0, acc0, acc2);
        float lo, hi;
        UNPACK2(lo, hi, acc0);
        float a = base + lo + hi;

        // gate activation (MUFU.TANH)
        float act = fmaf(act_s, tanh_fast(act_s * a), act_b);

        sAct[tid] = act;
        __syncthreads();

        // cell update, replicated in all warps (identical inputs -> identical c)
        float gi = sAct[j], gf = sAct[32 + j], gg = sAct[64 + j], go = sAct[96 + j];
        c = fmaf(gf, c, gi * gg);
        float hv = go * tanh_fast(c);

        sh[j] = hv;               // all warps write identical values (benign)
        __syncwarp();

        if (t < S_LEN - 1) {
            if (g == 0) gH[t * 32 + j] = hv;
        } else {
            float mu, sig;
            attn_step(hv, j, A, B, C, D, C2, D2, bo, wmu, bm, wsig, bs,
                      se[t], &mu, &sig, &sample);
            if (tid == 0) {
                out[HORIZ + t]         = mu;
                out[HORIZ + T_LEN + t] = sig;
                if (t < S_LEN - 1 + HORIZ)
                    out[t - (S_LEN - 1)] = sample;
            }
        }
    }
}

// ---------------------------------------------------------------------------
// Kernel 2: deferred attention for t = 0..510, one warp per t (all parallel).
// ---------------------------------------------------------------------------
extern "C" __global__ void deepar_att(
    const float* __restrict__ W_ef, const float* __restrict__ b_ef,
    const float* __restrict__ W_av, const float* __restrict__ b_av,
    const float* __restrict__ W_out,const float* __restrict__ b_out,
    const float* __restrict__ W_mu, const float* __restrict__ b_mu,
    const float* __restrict__ W_sig,const float* __restrict__ b_sig,
    float* __restrict__ out)
{
    const int warp = (blockIdx.x * blockDim.x + threadIdx.x) >> 5;
    const int lane = threadIdx.x & 31;
    if (warp >= S_LEN - 1) return;

    float wef = W_ef[lane], bef = b_ef[lane], wav = W_av[lane];
    float wo1 = W_out[lane], wo2 = W_out[32 + lane];
    float A  = warp_sum(wef * wav);
    float B  = warp_sum(bef * wav) + b_av[0];
    float C  = warp_sum(wef * wo1);
    float D  = warp_sum(bef * wo1);
    float C2 = warp_sum(wef * wo2);
    float D2 = warp_sum(bef * wo2);

    float h = gH[warp * 32 + lane];
    float mu, sig, samp;
    attn_step(h, lane, A, B, C, D, C2, D2, b_out[0],
              W_mu[lane], b_mu[0], W_sig[lane], b_sig[0],
              0.f, &mu, &sig, &samp);
    if (lane == 0) {
        out[HORIZ + warp]         = mu;
        out[HORIZ + T_LEN + warp] = sig;
    }
}

extern "C" void kernel_launch(void* const* d_in, const int* in_sizes, int n_in,
                              void* d_out, int out_size)
{
    const float* X     = (const float*)d_in[0];
    const float* y     = (const float*)d_in[1];
    const float* Xf    = (const float*)d_in[2];
    const float* eps   = (const float*)d_in[3];
    const float* W_ye  = (const float*)d_in[4];
    const float* b_ye  = (const float*)d_in[5];
    const float* W_ih  = (const float*)d_in[6];
    const float* W_hh  = (const float*)d_in[7];
    const float* b_ih  = (const float*)d_in[8];
    const float* b_hh  = (const float*)d_in[9];
    const float* W_ef  = (const float*)d_in[10];
    const float* b_ef  = (const float*)d_in[11];
    const float* W_av  = (const float*)d_in[12];
    const float* b_av  = (const float*)d_in[13];
    const float* W_out = (const float*)d_in[14];
    const float* b_out = (const float*)d_in[15];
    const float* W_mu  = (const float*)d_in[16];
    const float* b_mu  = (const float*)d_in[17];
    const float* W_sig = (const float*)d_in[18];
    const float* b_sig = (const float*)d_in[19];
    float* out = (float*)d_out;

    deepar_seq<<<1, 128>>>(X, y, Xf, eps, W_ye, b_ye, W_ih, W_hh, b_ih, b_hh,
                           W_ef, b_ef, W_av, b_av, W_out, b_out,
                           W_mu, b_mu, W_sig, b_sig, out);
    // 511 warps needed; 64 blocks x 256 threads = 512 warps
    deepar_att<<<64, 256>>>(W_ef, b_ef, W_av, b_av, W_out, b_out,
                            W_mu, b_mu, W_sig, b_sig, out);
}

// round 3
// speedup vs baseline: 2.6117x; 1.1190x over previous
#include <cuda_runtime.h>
#include <cstdint>

#define S_LEN 512
#define HORIZ 64
#define T_LEN 576   // S_LEN + HORIZ
#define HID   32
#define FEAT  4

// Scratch for deferred attention: h[t] for t = 0..510
__device__ float gH[S_LEN * HID];

// ---------------- packed f32x2 helpers ----------------
#define MUL2(d, a, b) \
    asm("mul.rn.f32x2 %0, %1, %2;" : "=l"(d) : "l"(a), "l"(b))
#define FMA2(d, a, b, c) \
    asm("fma.rn.f32x2 %0, %1, %2, %3;" : "=l"(d) : "l"(a), "l"(b), "l"(c))
#define ADD2(d, a, b) \
    asm("add.rn.f32x2 %0, %1, %2;" : "=l"(d) : "l"(a), "l"(b))
#define PACK2(d, lo, hi) \
    asm("mov.b64 %0, {%1, %2};" : "=l"(d) : "f"(lo), "f"(hi))
#define UNPACK2(lo, hi, v) \
    asm("mov.b64 {%0, %1}, %2;" : "=f"(lo), "=f"(hi) : "l"(v))

__device__ __forceinline__ float tanh_fast(float x) {
    float r; asm("tanh.approx.f32 %0, %1;" : "=f"(r) : "f"(x)); return r;
}

__device__ __forceinline__ float warp_sum(float v) {
#pragma unroll
    for (int d = 16; d; d >>= 1) v += __shfl_xor_sync(0xffffffffu, v, d);
    return v;
}

// Collapsed attention + output head, one warp, lane = hidden unit.
__device__ __forceinline__ void attn_step(
    float h, int lane,
    float A, float B, float C, float D, float C2, float D2,
    float bo, float wmu, float bm, float wsig, float bs,
    float epsv, float* mu_o, float* sig_o, float* samp_o)
{
    float av = __expf(fmaf(A, h, B));
    float rv = av * fmaf(C2, h, D2);
    float pa = av, pr = rv;
#pragma unroll
    for (int d = 1; d < 32; d <<= 1) {
        float ta = __shfl_up_sync(0xffffffffu, pa, d);
        float tr = __shfl_up_sync(0xffffffffu, pr, d);
        if (lane >= d) { pa += ta; pr += tr; }
    }
    float exa = pa - av;          // exclusive prefix of av
    float exr = pr - rv;          // exclusive prefix of r
    float o = tanh_fast(fmaf(C, h, D) + __fdividef(exr, exa + 1e-9f) + bo);
    float pm = o * wmu, ps = o * wsig;
#pragma unroll
    for (int d = 16; d; d >>= 1) {
        pm += __shfl_xor_sync(0xffffffffu, pm, d);
        ps += __shfl_xor_sync(0xffffffffu, ps, d);
    }
    float mu  = pm + bm;
    float sig = __logf(1.0f + __expf(ps + bs)) + 1e-6f;
    *mu_o = mu;
    *sig_o = sig;
    *samp_o = fmaf(sig, epsv, mu);
}

// ---------------------------------------------------------------------------
// Kernel 1: 4 warps. Warp g owns gate g (i,f,g,o); thread (g,j) owns gate row
// g*32+j. Cell state c_j replicated deterministically in all 4 warps.
// ---------------------------------------------------------------------------
extern "C" __global__ void __launch_bounds__(128, 1) deepar_seq(
    const float* __restrict__ X,    const float* __restrict__ y,
    const float* __restrict__ Xf,   const float* __restrict__ eps,
    const float* __restrict__ W_ye, const float* __restrict__ b_ye,
    const float* __restrict__ W_ih, const float* __restrict__ W_hh,
    const float* __restrict__ b_ih, const float* __restrict__ b_hh,
    const float* __restrict__ W_ef, const float* __restrict__ b_ef,
    const float* __restrict__ W_av, const float* __restrict__ b_av,
    const float* __restrict__ W_out,const float* __restrict__ b_out,
    const float* __restrict__ W_mu, const float* __restrict__ b_mu,
    const float* __restrict__ W_sig,const float* __restrict__ b_sig,
    float* __restrict__ out)
{
    __shared__ __align__(16) float sx[T_LEN * FEAT];
    __shared__ float sy[S_LEN];
    __shared__ float se[T_LEN];
    __shared__ __align__(16) float sh[HID];
    __shared__ __align__(16) float sActT[128];   // transposed: [unit*4 + gate]

    const int tid = threadIdx.x;
    const int g = tid >> 5;      // gate / warp id
    const int j = tid & 31;      // hidden unit / lane

    // ---- preload small inputs to shared ----
    for (int i = tid; i < S_LEN * FEAT; i += 128) sx[i] = X[i];
    for (int i = tid; i < HORIZ * FEAT; i += 128) sx[S_LEN * FEAT + i] = Xf[i];
    for (int i = tid; i < S_LEN; i += 128) sy[i] = y[i];
    for (int i = tid; i < T_LEN; i += 128) se[i] = eps[i];

    // ---- per-thread gate-row weights (packed f32x2 along k) ----
    // sigmoid gates (g != 2): fold the 0.5 pre-scale into ALL row inputs so
    // act = fma(0.5, tanh(a'), 0.5) directly (no extra MUL before MUFU).
    const int row = g * 32 + j;   // torch gate order: i,f,g,o
    const float scl = (g == 2) ? 1.0f : 0.5f;
    uint64_t wh2[16];
    {
        const float2* wr = (const float2*)(W_hh + row * 32);
#pragma unroll
        for (int k = 0; k < 16; k++) {
            float2 v = wr[k];
            PACK2(wh2[k], v.x * scl, v.y * scl);
        }
    }
    float wx0 = W_ih[row * 36 + 0] * scl, wx1 = W_ih[row * 36 + 1] * scl;
    float wx2 = W_ih[row * 36 + 2] * scl, wx3 = W_ih[row * 36 + 3] * scl;
    float ug = 0.f, bg = b_ih[row] + b_hh[row];
#pragma unroll
    for (int k = 0; k < 32; k++) {
        float w = W_ih[row * 36 + 4 + k];
        ug = fmaf(w, W_ye[k], ug);
        bg = fmaf(w, b_ye[k], bg);
    }
    ug *= scl; bg *= scl;
    const float as2 = scl;                     // post-tanh scale
    const float ab2 = (g == 2) ? 0.0f : 0.5f;  // post-tanh bias

    // ---- collapsed attention scalars (identical in every warp) ----
    float wef = W_ef[j], bef = b_ef[j], wav = W_av[j];
    float wo1 = W_out[j], wo2 = W_out[32 + j];
    float A  = warp_sum(wef * wav);
    float B  = warp_sum(bef * wav) + b_av[0];
    float C  = warp_sum(wef * wo1);
    float D  = warp_sum(bef * wo1);
    float C2 = warp_sum(wef * wo2);
    float D2 = warp_sum(bef * wo2);
    float bo = b_out[0], bm = b_mu[0], bs = b_sig[0];
    float wmu = W_mu[j], wsig = W_sig[j];

    uint32_t sh_addr, sat_addr;
    asm("{ .reg .u64 t0; cvta.to.shared.u64 t0, %1; cvt.u32.u64 %0, t0; }"
        : "=r"(sh_addr) : "l"(sh));
    asm("{ .reg .u64 t0; cvta.to.shared.u64 t0, %1; cvt.u32.u64 %0, t0; }"
        : "=r"(sat_addr) : "l"(sActT));
    const uint32_t sat_my = sat_addr + (uint32_t)(j * 4 + g) * 4u;
    const uint32_t sat_v4 = sat_addr + (uint32_t)j * 16u;

    float c = 0.f, sample = 0.f;
    if (tid < 32) sh[tid] = 0.f;
    __syncthreads();

    // One LSTM step: dot -> act -> exchange -> cell -> publish h.
    // Returns nothing; updates c (by ref pattern via macro-ish lambda).
#define LSTM_STEP(T_IDX, YIN, HV_OUT)                                         \
    {                                                                         \
        /* h pairs from shared: 8 x 16B broadcast loads */                    \
        uint64_t hp[16];                                                      \
        _Pragma("unroll")                                                     \
        for (int q = 0; q < 8; q++)                                           \
            asm volatile("ld.shared.v2.b64 {%0, %1}, [%2];"                   \
                         : "=l"(hp[2*q]), "=l"(hp[2*q+1])                     \
                         : "r"(sh_addr + 16u * q));                           \
        float4 xv = ((const float4*)sx)[T_IDX];                               \
        float base = fmaf(ug, (YIN), bg);                                     \
        base = fmaf(wx0, xv.x, base);                                         \
        base = fmaf(wx1, xv.y, base);                                         \
        base = fmaf(wx2, xv.z, base);                                         \
        base = fmaf(wx3, xv.w, base);                                         \
        uint64_t acc0, acc1, acc2, acc3, bp;                                  \
        PACK2(bp, base, 0.0f);                                                \
        FMA2(acc0, wh2[0], hp[0], bp);                                        \
        MUL2(acc1, wh2[1], hp[1]);                                            \
        MUL2(acc2, wh2[2], hp[2]);                                            \
        MUL2(acc3, wh2[3], hp[3]);                                            \
        _Pragma("unroll")                                                     \
        for (int s = 1; s < 4; s++) {                                         \
            FMA2(acc0, wh2[s*4+0], hp[s*4+0], acc0);                          \
            FMA2(acc1, wh2[s*4+1], hp[s*4+1], acc1);                          \
            FMA2(acc2, wh2[s*4+2], hp[s*4+2], acc2);                          \
            FMA2(acc3, wh2[s*4+3], hp[s*4+3], acc3);                          \
        }                                                                     \
        ADD2(acc0, acc0, acc1);                                               \
        ADD2(acc2, acc2, acc3);                                               \
        ADD2(acc0, acc0, acc2);                                               \
        float lo_, hi_;                                                       \
        UNPACK2(lo_, hi_, acc0);                                              \
        float a_ = lo_ + hi_;                                                 \
        float act_ = fmaf(as2, tanh_fast(a_), ab2);                           \
        asm volatile("st.shared.f32 [%0], %1;" :: "r"(sat_my), "f"(act_));    \
        __syncthreads();                                                      \
        float gi_, gf_, gg_, go_;                                             \
        asm volatile("ld.shared.v4.f32 {%0,%1,%2,%3}, [%4];"                  \
                     : "=f"(gi_), "=f"(gf_), "=f"(gg_), "=f"(go_)             \
                     : "r"(sat_v4));                                          \
        c = fmaf(gf_, c, gi_ * gg_);                                          \
        float hv_ = go_ * tanh_fast(c);                                       \
        asm volatile("st.shared.f32 [%0], %1;"                               \
                     :: "r"(sh_addr + (uint32_t)j * 4u), "f"(hv_));           \
        __syncwarp();                                                         \
        HV_OUT = hv_;                                                         \
    }

    // ---- segment 1: t = 0..510, LSTM only, yin = y[t], h deferred ----
#pragma unroll 2
    for (int t = 0; t < S_LEN - 1; t++) {
        float hv;
        LSTM_STEP(t, sy[t], hv);
        if (g == 0) gH[t * 32 + j] = hv;
    }

    // ---- segment 2+3: t = 511..575, inline attention, sample feedback ----
    for (int t = S_LEN - 1; t < T_LEN; t++) {
        float yin = (t < S_LEN) ? sy[t] : sample;
        float hv;
        LSTM_STEP(t, yin, hv);
        float mu, sig;
        attn_step(hv, j, A, B, C, D, C2, D2, bo, wmu, bm, wsig, bs,
                  se[t], &mu, &sig, &sample);
        if (tid == 0) {
            out[HORIZ + t]         = mu;
            out[HORIZ + T_LEN + t] = sig;
            if (t < S_LEN - 1 + HORIZ)
                out[t - (S_LEN - 1)] = sample;
        }
    }
#undef LSTM_STEP
}

// ---------------------------------------------------------------------------
// Kernel 2: deferred attention for t = 0..510, one warp per t (all parallel).
// ---------------------------------------------------------------------------
extern "C" __global__ void deepar_att(
    const float* __restrict__ W_ef, const float* __restrict__ b_ef,
    const float* __restrict__ W_av, const float* __restrict__ b_av,
    const float* __restrict__ W_out,const float* __restrict__ b_out,
    const float* __restrict__ W_mu, const float* __restrict__ b_mu,
    const float* __restrict__ W_sig,const float* __restrict__ b_sig,
    float* __restrict__ out)
{
    const int warp = (blockIdx.x * blockDim.x + threadIdx.x) >> 5;
    const int lane = threadIdx.x & 31;
    if (warp >= S_LEN - 1) return;

    float wef = W_ef[lane], bef = b_ef[lane], wav = W_av[lane];
    float wo1 = W_out[lane], wo2 = W_out[32 + lane];
    float A  = warp_sum(wef * wav);
    float B  = warp_sum(bef * wav) + b_av[0];
    float C  = warp_sum(wef * wo1);
    float D  = warp_sum(bef * wo1);
    float C2 = warp_sum(wef * wo2);
    float D2 = warp_sum(bef * wo2);

    float h = gH[warp * 32 + lane];
    float mu, sig, samp;
    attn_step(h, lane, A, B, C, D, C2, D2, b_out[0],
              W_mu[lane], b_mu[0], W_sig[lane], b_sig[0],
              0.f, &mu, &sig, &samp);
    if (lane == 0) {
        out[HORIZ + warp]         = mu;
        out[HORIZ + T_LEN + warp] = sig;
    }
}

extern "C" void kernel_launch(void* const* d_in, const int* in_sizes, int n_in,
                              void* d_out, int out_size)
{
    const float* X     = (const float*)d_in[0];
    const float* y     = (const float*)d_in[1];
    const float* Xf    = (const float*)d_in[2];
    const float* eps   = (const float*)d_in[3];
    const float* W_ye  = (const float*)d_in[4];
    const float* b_ye  = (const float*)d_in[5];
    const float* W_ih  = (const float*)d_in[6];
    const float* W_hh  = (const float*)d_in[7];
    const float* b_ih  = (const float*)d_in[8];
    const float* b_hh  = (const float*)d_in[9];
    const float* W_ef  = (const float*)d_in[10];
    const float* b_ef  = (const float*)d_in[11];
    const float* W_av  = (const float*)d_in[12];
    const float* b_av  = (const float*)d_in[13];
    const float* W_out = (const float*)d_in[14];
    const float* b_out = (const float*)d_in[15];
    const float* W_mu  = (const float*)d_in[16];
    const float* b_mu  = (const float*)d_in[17];
    const float* W_sig = (const float*)d_in[18];
    const float* b_sig = (const float*)d_in[19];
    float* out = (float*)d_out;

    deepar_seq<<<1, 128>>>(X, y, Xf, eps, W_ye, b_ye, W_ih, W_hh, b_ih, b_hh,
                           W_ef, b_ef, W_av, b_av, W_out, b_out,
                           W_mu, b_mu, W_sig, b_sig, out);
    // 511 warps needed; 64 blocks x 256 threads = 512 warps
    deepar_att<<<64, 256>>>(W_ef, b_ef, W_av, b_av, W_out, b_out,
                            W_mu, b_mu, W_sig, b_sig, out);
}